// round 1
// baseline (speedup 1.0000x reference)
#include <cuda_runtime.h>

#define B    32
#define D    1024   // CTX_DIM
#define C    2048   // CTX_SIZE
#define H    1024   // HID
#define HC   32     // h-chunks in kernel A
#define HCH  (H/HC) // 32 h per chunk
#define CCH  32     // context columns per chunk in kernel C
#define NCH  (C/CCH)// 64 chunks per batch
#define SMROW 33    // padded smem row (conflict-free)

// ---- scratch (no allocations allowed) ----
__device__ float g_pv[HC * B * D];     // 4 MB  partial v
__device__ float g_v[B * D];           // 128 KB v[b,d]
__device__ float g_pacc[B * NCH * D];  // 8 MB  per-chunk weighted partial sums
__device__ float g_pm[B * NCH];        // per-chunk max
__device__ float g_pz[B * NCH];        // per-chunk Z (unnormalized)

// ---------- Kernel A: partial v[b,d] = sum_{h in chunk} W[h,d]*hidden[b,h] ----------
__global__ void vpart_kernel(const float* __restrict__ W, const float* __restrict__ hid) {
    __shared__ float sh[B][HCH];
    const int tid = threadIdx.x;                 // 128 threads
    const int d   = blockIdx.x * 128 + tid;      // 8 d-tiles
    const int h0  = blockIdx.y * HCH;            // 32 h-chunks
    for (int i = tid; i < B * HCH; i += 128) {
        int b = i / HCH, h = i % HCH;
        sh[b][h] = hid[b * H + h0 + h];
    }
    __syncthreads();
    float acc[B];
#pragma unroll
    for (int b = 0; b < B; b++) acc[b] = 0.f;
    for (int h = 0; h < HCH; h++) {
        float w = W[(size_t)(h0 + h) * D + d];
#pragma unroll
        for (int b = 0; b < B; b++) acc[b] += w * sh[b][h];
    }
    float* outp = g_pv + (size_t)blockIdx.y * (B * D);
#pragma unroll
    for (int b = 0; b < B; b++) outp[b * D + d] = acc[b];
}

// ---------- Kernel B: reduce partials -> g_v ----------
__global__ void vreduce_kernel() {
    int i = blockIdx.x * 1024 + threadIdx.x;     // 32 blocks x 1024
    float s = 0.f;
#pragma unroll
    for (int hc = 0; hc < HC; hc++) s += g_pv[(size_t)hc * (B * D) + i];
    g_v[i] = s;
}

// ---------- Kernel C: fused scores + local softmax + weighted partial sum ----------
extern __shared__ float smem[];
__global__ void __launch_bounds__(256, 1) main_kernel(const float* __restrict__ ctx) {
    float* sm  = smem;                 // D * SMROW
    float* v_s = sm + D * SMROW;       // D
    float* red = v_s + D;              // 8 * 32
    float* ws  = red + 256;            // 32

    const int tid = threadIdx.x;       // 256 threads
    const int b   = blockIdx.y;
    const int ch  = blockIdx.x;        // 0..NCH-1
    const int c0  = ch * CCH;

    for (int i = tid; i < D; i += 256) v_s[i] = g_v[b * D + i];
    __syncthreads();

    // Phase 0+1: stream tile to smem, fuse score accumulation.
    const int c  = tid & 31;           // lane -> column (coalesced 128B/warp)
    const int dg = tid >> 5;           // warp -> d phase
    const float* src = ctx + (size_t)b * D * C + c0 + c;
    float psc = 0.f;
#pragma unroll 4
    for (int d = dg; d < D; d += 8) {
        float x = __ldg(&src[(size_t)d * C]);
        sm[d * SMROW + c] = x;
        psc += x * v_s[d];
    }
    red[dg * 32 + c] = psc;
    __syncthreads();

    // warp 0: finish 32 scores, local softmax stats
    if (tid < 32) {
        float s = 0.f;
#pragma unroll
        for (int g = 0; g < 8; g++) s += red[g * 32 + tid];
        float m = s;
#pragma unroll
        for (int o = 16; o > 0; o >>= 1) m = fmaxf(m, __shfl_xor_sync(0xffffffffu, m, o));
        float e = __expf(s - m);
        float z = e;
#pragma unroll
        for (int o = 16; o > 0; o >>= 1) z += __shfl_xor_sync(0xffffffffu, z, o);
        ws[tid] = e;                   // unnormalized weights
        if (tid == 0) { g_pm[b * NCH + ch] = m; g_pz[b * NCH + ch] = z; }
    }
    __syncthreads();

    // Phase 2: weighted column sum from smem (conflict-free: row pad 33)
    float wreg[CCH];
#pragma unroll
    for (int j = 0; j < CCH; j++) wreg[j] = ws[j];
#pragma unroll
    for (int k = 0; k < 4; k++) {
        int d = tid + 256 * k;
        float a = 0.f;
#pragma unroll
        for (int j = 0; j < CCH; j++) a += sm[d * SMROW + j] * wreg[j];
        g_pacc[((size_t)b * NCH + ch) * D + d] = a;
    }
}

// ---------- Kernel D: combine chunks + broadcast over seqlen ----------
__global__ void combine_kernel(float* __restrict__ out, int seqlen) {
    __shared__ float pmsh[NCH], pzsh[NCH], fsh[NCH];
    const int b = blockIdx.x, tid = threadIdx.x;   // 256 threads
    if (tid < NCH) { pmsh[tid] = g_pm[b * NCH + tid]; pzsh[tid] = g_pz[b * NCH + tid]; }
    __syncthreads();
    float M = -1e30f;
#pragma unroll
    for (int ch = 0; ch < NCH; ch++) M = fmaxf(M, pmsh[ch]);
    float Z = 0.f;
#pragma unroll
    for (int ch = 0; ch < NCH; ch++) Z += pzsh[ch] * __expf(pmsh[ch] - M);
    if (tid < NCH) fsh[tid] = __expf(pmsh[tid] - M);
    __syncthreads();
    const float inv = 1.0f / Z;
#pragma unroll
    for (int k = 0; k < 4; k++) {
        int d = tid + 256 * k;
        float val = 0.f;
        for (int ch = 0; ch < NCH; ch++)
            val += g_pacc[((size_t)b * NCH + ch) * D + d] * fsh[ch];
        val *= inv;
        for (int s = 0; s < seqlen; s++)
            out[((size_t)s * B + b) * D + d] = val;
    }
}

extern "C" void kernel_launch(void* const* d_in, const int* in_sizes, int n_in,
                              void* d_out, int out_size) {
    // inputs: [0]=seqlen(int32), [1]=hidden f32 [1,B,H], [2]=contextvects f32 [B,D,C],
    //         [3]=W f32 [H,D], [4]=b f32 [H] (bias is softmax-invariant -> unused)
    const float* hid = (const float*)d_in[1];
    const float* ctx = (const float*)d_in[2];
    const float* W   = (const float*)d_in[3];
    float* out = (float*)d_out;
    const int seqlen = out_size / (B * H);

    vpart_kernel<<<dim3(8, HC), 128>>>(W, hid);
    vreduce_kernel<<<32, 1024>>>();

    const size_t smemC = (size_t)(D * SMROW + D + 256 + 32) * sizeof(float); // ~140.4 KB
    cudaFuncSetAttribute(main_kernel, cudaFuncAttributeMaxDynamicSharedMemorySize, (int)smemC);
    main_kernel<<<dim3(NCH, B), 256, smemC>>>(ctx);

    combine_kernel<<<B, 256>>>(out, seqlen);
}

// round 2
// speedup vs baseline: 2.8401x; 2.8401x over previous
#include <cuda_runtime.h>

#define B    32
#define D    1024   // CTX_DIM
#define C    2048   // CTX_SIZE
#define H    1024   // HID
#define HC   32     // h-chunks in kernel A
#define HCH  (H/HC) // 32 h per chunk
#define CCH  32     // context columns per chunk in kernel C
#define NCH  (C/CCH)// 64 chunks per batch
#define SMROW 33    // padded smem row (conflict-free)

// ---- scratch (no allocations allowed) ----
__device__ float g_pv[HC * B * D];     // 4 MB  partial v
__device__ float g_v[B * D];           // 128 KB v[b,d]
__device__ float g_pacc[B * NCH * D];  // 8 MB  per-chunk weighted partial sums
__device__ float g_pm[B * NCH];        // per-chunk max
__device__ float g_pz[B * NCH];        // per-chunk Z (unnormalized)
__device__ float g_ctx[B * D];         // final context vector before broadcast

// ---------- Kernel A: partial v[b,d] = sum_{h in chunk} W[h,d]*hidden[b,h] ----------
__global__ void vpart_kernel(const float* __restrict__ W, const float* __restrict__ hid) {
    __shared__ float sh[B][HCH];
    const int tid = threadIdx.x;                 // 128 threads
    const int d   = blockIdx.x * 128 + tid;      // 8 d-tiles
    const int h0  = blockIdx.y * HCH;            // 32 h-chunks
    for (int i = tid; i < B * HCH; i += 128) {
        int b = i / HCH, h = i % HCH;
        sh[b][h] = hid[b * H + h0 + h];
    }
    __syncthreads();
    float acc[B];
#pragma unroll
    for (int b = 0; b < B; b++) acc[b] = 0.f;
    for (int h = 0; h < HCH; h++) {
        float w = W[(size_t)(h0 + h) * D + d];
#pragma unroll
        for (int b = 0; b < B; b++) acc[b] += w * sh[b][h];
    }
    float* outp = g_pv + (size_t)blockIdx.y * (B * D);
#pragma unroll
    for (int b = 0; b < B; b++) outp[b * D + d] = acc[b];
}

// ---------- Kernel B: reduce partials -> g_v ----------
__global__ void vreduce_kernel() {
    int i = blockIdx.x * 1024 + threadIdx.x;     // 32 blocks x 1024
    float s = 0.f;
#pragma unroll
    for (int hc = 0; hc < HC; hc++) s += g_pv[(size_t)hc * (B * D) + i];
    g_v[i] = s;
}

// ---------- Kernel C: fused scores + local softmax + weighted partial sum ----------
// 1024 threads/CTA: 32 warps in flight per SM -> latency hidden, DRAM-bound.
extern __shared__ float smem[];
__global__ void __launch_bounds__(1024, 1) main_kernel(const float* __restrict__ ctx) {
    float* sm  = smem;                 // D * SMROW  (33792 floats)
    float* v_s = sm + D * SMROW;       // D
    float* red = v_s + D;              // 32 warps * 32 lanes
    float* ws  = red + 1024;           // 32

    const int tid  = threadIdx.x;      // 1024 threads
    const int lane = tid & 31;
    const int w    = tid >> 5;         // warp id 0..31
    const int b    = blockIdx.y;
    const int ch   = blockIdx.x;       // 0..NCH-1
    const int c0   = ch * CCH;

    v_s[tid] = g_v[b * D + tid];       // blockDim == D
    __syncthreads();

    // Phase 1: stream tile to smem, fuse score accumulation.
    // warp w handles rows d = w, w+32, ... (32 consecutive rows active at once)
    const float* src = ctx + (size_t)b * D * C + c0 + lane;
    float psc = 0.f;
#pragma unroll 8
    for (int i = 0; i < 32; i++) {
        int d = w + 32 * i;
        float x = __ldg(&src[(size_t)d * C]);
        sm[d * SMROW + lane] = x;
        psc += x * v_s[d];
    }
    red[w * 32 + lane] = psc;
    __syncthreads();

    // warp 0: finish 32 scores, local softmax stats
    if (tid < 32) {
        float s = 0.f;
#pragma unroll
        for (int g = 0; g < 32; g++) s += red[g * 32 + tid];
        float m = s;
#pragma unroll
        for (int o = 16; o > 0; o >>= 1) m = fmaxf(m, __shfl_xor_sync(0xffffffffu, m, o));
        float e = __expf(s - m);
        float z = e;
#pragma unroll
        for (int o = 16; o > 0; o >>= 1) z += __shfl_xor_sync(0xffffffffu, z, o);
        ws[tid] = e;                   // unnormalized weights
        if (tid == 0) { g_pm[b * NCH + ch] = m; g_pz[b * NCH + ch] = z; }
    }
    __syncthreads();

    // Phase 2: weighted column sum from smem, one d per thread (conflict-free pad-33)
    float a = 0.f;
#pragma unroll
    for (int j = 0; j < CCH; j++) a += sm[tid * SMROW + j] * ws[j];
    g_pacc[((size_t)b * NCH + ch) * D + tid] = a;
}

// ---------- Kernel D1: combine chunk partials -> g_ctx[b,d] ----------
__global__ void combine_kernel() {
    __shared__ float fsh[NCH];
    __shared__ float pmsh[NCH], pzsh[NCH];
    const int b = blockIdx.x, tid = threadIdx.x;   // grid (B, 4), 256 threads
    if (tid < NCH) { pmsh[tid] = g_pm[b * NCH + tid]; pzsh[tid] = g_pz[b * NCH + tid]; }
    __syncthreads();
    float M = -1e30f;
#pragma unroll
    for (int ch = 0; ch < NCH; ch++) M = fmaxf(M, pmsh[ch]);
    float Z = 0.f;
#pragma unroll
    for (int ch = 0; ch < NCH; ch++) Z += pzsh[ch] * __expf(pmsh[ch] - M);
    if (tid < NCH) fsh[tid] = __expf(pmsh[tid] - M);
    __syncthreads();
    const float inv = 1.0f / Z;
    const int d = blockIdx.y * 256 + tid;
    float val = 0.f;
#pragma unroll 8
    for (int ch = 0; ch < NCH; ch++)
        val += g_pacc[((size_t)b * NCH + ch) * D + d] * fsh[ch];
    g_ctx[b * D + d] = val * inv;
}

// ---------- Kernel D2: broadcast over seqlen (pure BW write) ----------
__global__ void bcast_kernel(float* __restrict__ out, int total) {
    int i = blockIdx.x * 1024 + threadIdx.x;
    if (i < total) out[i] = g_ctx[i & (B * D - 1)];
}

extern "C" void kernel_launch(void* const* d_in, const int* in_sizes, int n_in,
                              void* d_out, int out_size) {
    // inputs: [0]=seqlen(int32), [1]=hidden f32 [1,B,H], [2]=contextvects f32 [B,D,C],
    //         [3]=W f32 [H,D], [4]=b f32 [H] (bias is softmax-invariant -> unused)
    const float* hid = (const float*)d_in[1];
    const float* ctx = (const float*)d_in[2];
    const float* W   = (const float*)d_in[3];
    float* out = (float*)d_out;

    vpart_kernel<<<dim3(8, HC), 128>>>(W, hid);
    vreduce_kernel<<<32, 1024>>>();

    const size_t smemC = (size_t)(D * SMROW + D + 1024 + 32) * sizeof(float); // ~143 KB
    cudaFuncSetAttribute(main_kernel, cudaFuncAttributeMaxDynamicSharedMemorySize, (int)smemC);
    main_kernel<<<dim3(NCH, B), 1024, smemC>>>(ctx);

    combine_kernel<<<dim3(B, 4), 256>>>();

    const int total = out_size;
    bcast_kernel<<<(total + 1023) / 1024, 1024>>>(out, total);
}

// round 3
// speedup vs baseline: 3.9970x; 1.4074x over previous
#include <cuda_runtime.h>

#define B    32
#define D    1024   // CTX_DIM
#define C    2048   // CTX_SIZE
#define H    1024   // HID
#define HC   32     // h-chunks in kernel A
#define HCH  (H/HC) // 32 h per chunk
#define CCH  32     // context columns per chunk in kernel C
#define NCH  (C/CCH)// 64 chunks per batch

// ---- scratch (no allocations allowed) ----
__device__ float g_pv[HC * B * D];     // 4 MB  partial v
__device__ float g_v[B * D];           // 128 KB v[b,d]
__device__ float g_pacc[B * NCH * D];  // 8 MB  per-chunk weighted partial sums
__device__ float g_pm[B * NCH];        // per-chunk max
__device__ float g_pz[B * NCH];        // per-chunk Z (unnormalized)
__device__ float g_cpart[4][B * D];    // 4-way split combine partials
__device__ float g_inv[B];             // 1/Z per batch

// ---------- Kernel A: partial v[b,d] = sum_{h in chunk} W[h,d]*hidden[b,h] ----------
__global__ void vpart_kernel(const float* __restrict__ W, const float* __restrict__ hid) {
    __shared__ float sh[B][HCH];
    const int tid = threadIdx.x;                 // 128 threads
    const int d   = blockIdx.x * 128 + tid;      // 8 d-tiles
    const int h0  = blockIdx.y * HCH;            // 32 h-chunks
    for (int i = tid; i < B * HCH; i += 128) {
        int b = i / HCH, h = i % HCH;
        sh[b][h] = hid[b * H + h0 + h];
    }
    __syncthreads();
    float acc[B];
#pragma unroll
    for (int b = 0; b < B; b++) acc[b] = 0.f;
#pragma unroll 8
    for (int h = 0; h < HCH; h++) {
        float w = W[(size_t)(h0 + h) * D + d];
#pragma unroll
        for (int b = 0; b < B; b++) acc[b] += w * sh[b][h];
    }
    float* outp = g_pv + (size_t)blockIdx.y * (B * D);
#pragma unroll
    for (int b = 0; b < B; b++) outp[b * D + d] = acc[b];
}

// ---------- Kernel B: reduce partials -> g_v ----------
__global__ void vreduce_kernel() {
    int i = blockIdx.x * 1024 + threadIdx.x;     // 32 blocks x 1024
    float s = 0.f;
#pragma unroll
    for (int hc = 0; hc < HC; hc++) s += g_pv[(size_t)hc * (B * D) + i];
    g_v[i] = s;
}

// ---------- Kernel C: register-resident tile, fused scores + weighted partials ----------
// Thread (w, r, cq): rows d_i = i*128 + w*4 + r (i=0..8), cols c0 + 4*cq + k (k=0..4).
__global__ void __launch_bounds__(1024, 1) main_kernel(const float* __restrict__ ctx) {
    __shared__ float red[32 * 32];
    __shared__ float ws[32];
    __shared__ float sm_acc[D];

    const int tid  = threadIdx.x;       // 1024
    const int lane = tid & 31;
    const int w    = tid >> 5;
    const int r    = lane >> 3;         // 0..3
    const int cq   = lane & 7;          // 0..7
    const int b    = blockIdx.y;
    const int ch   = blockIdx.x;        // 0..NCH-1

    const int drow = w * 4 + r;         // 0..127
    const float* base = ctx + (size_t)b * D * C + (size_t)drow * C + ch * CCH + 4 * cq;

    // Load 8 float4 (rows drow + 128*i), fully independent -> huge MLP.
    float4 x[8];
#pragma unroll
    for (int i = 0; i < 8; i++)
        x[i] = *reinterpret_cast<const float4*>(base + (size_t)i * 128 * C);

    float vr[8];
#pragma unroll
    for (int i = 0; i < 8; i++)
        vr[i] = __ldg(&g_v[b * D + i * 128 + drow]);

    // Phase 1: per-column partial scores
    float p0 = 0.f, p1 = 0.f, p2 = 0.f, p3 = 0.f;
#pragma unroll
    for (int i = 0; i < 8; i++) {
        p0 += x[i].x * vr[i];  p1 += x[i].y * vr[i];
        p2 += x[i].z * vr[i];  p3 += x[i].w * vr[i];
    }
    // reduce over r (lane bits 3,4)
#pragma unroll
    for (int o = 8; o <= 16; o <<= 1) {
        p0 += __shfl_xor_sync(0xffffffffu, p0, o);
        p1 += __shfl_xor_sync(0xffffffffu, p1, o);
        p2 += __shfl_xor_sync(0xffffffffu, p2, o);
        p3 += __shfl_xor_sync(0xffffffffu, p3, o);
    }
    if (r == 0) {
        red[w * 32 + 4 * cq + 0] = p0;
        red[w * 32 + 4 * cq + 1] = p1;
        red[w * 32 + 4 * cq + 2] = p2;
        red[w * 32 + 4 * cq + 3] = p3;
    }
    __syncthreads();

    // warp 0: finish 32 scores, local softmax stats
    if (tid < 32) {
        float s = 0.f;
#pragma unroll
        for (int g = 0; g < 32; g++) s += red[g * 32 + tid];
        float m = s;
#pragma unroll
        for (int o = 16; o > 0; o >>= 1) m = fmaxf(m, __shfl_xor_sync(0xffffffffu, m, o));
        float e = __expf(s - m);
        float z = e;
#pragma unroll
        for (int o = 16; o > 0; o >>= 1) z += __shfl_xor_sync(0xffffffffu, z, o);
        ws[tid] = e;
        if (tid == 0) { g_pm[b * NCH + ch] = m; g_pz[b * NCH + ch] = z; }
    }
    __syncthreads();

    // Phase 2: weighted column sum from registers
    const float w0 = ws[4 * cq + 0], w1 = ws[4 * cq + 1];
    const float w2 = ws[4 * cq + 2], w3 = ws[4 * cq + 3];
#pragma unroll
    for (int i = 0; i < 8; i++) {
        float t = x[i].x * w0 + x[i].y * w1 + x[i].z * w2 + x[i].w * w3;
        t += __shfl_xor_sync(0xffffffffu, t, 1);
        t += __shfl_xor_sync(0xffffffffu, t, 2);
        t += __shfl_xor_sync(0xffffffffu, t, 4);
        if (cq == 0) sm_acc[i * 128 + drow] = t;
    }
    __syncthreads();
    g_pacc[(size_t)(b * NCH + ch) * D + tid] = sm_acc[tid];
}

// ---------- Kernel D1: combine (split 4-way over chunks) ----------
__global__ void combine_kernel() {
    __shared__ float pmsh[NCH], pzsh[NCH], fsh[NCH];
    const int b   = blockIdx.x;
    const int dg  = blockIdx.y & 3;        // d group (0..3)
    const int chg = blockIdx.y >> 2;       // chunk group (0..3)
    const int tid = threadIdx.x;           // 256
    if (tid < NCH) { pmsh[tid] = g_pm[b * NCH + tid]; pzsh[tid] = g_pz[b * NCH + tid]; }
    __syncthreads();
    float M = -1e30f;
#pragma unroll
    for (int ch = 0; ch < NCH; ch++) M = fmaxf(M, pmsh[ch]);
    float Z = 0.f;
#pragma unroll
    for (int ch = 0; ch < NCH; ch++) Z += pzsh[ch] * __expf(pmsh[ch] - M);
    if (tid < NCH) fsh[tid] = __expf(pmsh[tid] - M);
    __syncthreads();
    if (chg == 0 && dg == 0 && tid == 0) g_inv[b] = 1.0f / Z;

    const int d = dg * 256 + tid;
    float val = 0.f;
#pragma unroll
    for (int j = 0; j < 16; j++) {
        int ch = chg * 16 + j;
        val += g_pacc[(size_t)(b * NCH + ch) * D + d] * fsh[ch];
    }
    g_cpart[chg][b * D + d] = val;
}

// ---------- Kernel D2: sum partials, normalize, broadcast over seqlen ----------
__global__ void bcast_kernel(float4* __restrict__ out, int total4) {
    int i = blockIdx.x * 256 + threadIdx.x;
    if (i >= total4) return;
    int j = i & (B * D / 4 - 1);           // float4 index within one [B,D] slab
    int b = j >> 8;                        // D/4 = 256 float4 per batch row
    const float4 a0 = reinterpret_cast<const float4*>(g_cpart[0])[j];
    const float4 a1 = reinterpret_cast<const float4*>(g_cpart[1])[j];
    const float4 a2 = reinterpret_cast<const float4*>(g_cpart[2])[j];
    const float4 a3 = reinterpret_cast<const float4*>(g_cpart[3])[j];
    const float inv = g_inv[b];
    float4 o;
    o.x = (a0.x + a1.x + a2.x + a3.x) * inv;
    o.y = (a0.y + a1.y + a2.y + a3.y) * inv;
    o.z = (a0.z + a1.z + a2.z + a3.z) * inv;
    o.w = (a0.w + a1.w + a2.w + a3.w) * inv;
    out[i] = o;
}

extern "C" void kernel_launch(void* const* d_in, const int* in_sizes, int n_in,
                              void* d_out, int out_size) {
    // inputs: [0]=seqlen(int32), [1]=hidden f32 [1,B,H], [2]=contextvects f32 [B,D,C],
    //         [3]=W f32 [H,D], [4]=b f32 [H] (bias is softmax-invariant -> unused)
    const float* hid = (const float*)d_in[1];
    const float* ctx = (const float*)d_in[2];
    const float* W   = (const float*)d_in[3];

    vpart_kernel<<<dim3(8, HC), 128>>>(W, hid);
    vreduce_kernel<<<32, 1024>>>();

    main_kernel<<<dim3(NCH, B), 1024>>>(ctx);

    combine_kernel<<<dim3(B, 16), 256>>>();

    const int total4 = out_size / 4;
    bcast_kernel<<<(total4 + 255) / 256, 256>>>((float4*)d_out, total4);
}

// round 4
// speedup vs baseline: 4.2296x; 1.0582x over previous
#include <cuda_runtime.h>

#define B    32
#define D    1024   // CTX_DIM
#define C    2048   // CTX_SIZE
#define H    1024   // HID
#define HC   32     // h-chunks in kernel A
#define HCH  (H/HC) // 32 h per chunk
#define CCH  16     // context columns per chunk in kernel C
#define NCH  (C/CCH)// 128 chunks per batch
#define NCHG 4      // combine chunk groups
#define CPG  (NCH/NCHG) // 32 chunks per group

// ---- scratch (no allocations allowed) ----
__device__ float g_pv[HC * B * D];       // 4 MB  partial v
__device__ float g_v[B * D];             // 128 KB v[b,d]
__device__ float g_pacc[B * NCH * D];    // 16 MB per-chunk weighted partial sums
__device__ float g_pm[B * NCH];          // per-chunk max
__device__ float g_pz[B * NCH];          // per-chunk Z (unnormalized)
__device__ float g_cpart[NCHG][B * D];   // combine partials
__device__ float g_inv[B];               // 1/Z per batch

// ---------- Kernel A: partial v[b,d] = sum_{h in chunk} W[h,d]*hidden[b,h] ----------
__global__ void vpart_kernel(const float* __restrict__ W, const float* __restrict__ hid) {
    __shared__ float sh[B][HCH];
    const int tid = threadIdx.x;                 // 128 threads
    const int d   = blockIdx.x * 128 + tid;      // 8 d-tiles
    const int h0  = blockIdx.y * HCH;            // 32 h-chunks
    for (int i = tid; i < B * HCH; i += 128) {
        int b = i / HCH, h = i % HCH;
        sh[b][h] = hid[b * H + h0 + h];
    }
    __syncthreads();
    float acc[B];
#pragma unroll
    for (int b = 0; b < B; b++) acc[b] = 0.f;
#pragma unroll 8
    for (int h = 0; h < HCH; h++) {
        float w = W[(size_t)(h0 + h) * D + d];
#pragma unroll
        for (int b = 0; b < B; b++) acc[b] += w * sh[b][h];
    }
    float* outp = g_pv + (size_t)blockIdx.y * (B * D);
#pragma unroll
    for (int b = 0; b < B; b++) outp[b * D + d] = acc[b];
}

// ---------- Kernel B: reduce partials -> g_v ----------
__global__ void vreduce_kernel() {
    int i = blockIdx.x * 1024 + threadIdx.x;     // 32 blocks x 1024
    float s = 0.f;
#pragma unroll
    for (int hc = 0; hc < HC; hc++) s += g_pv[(size_t)hc * (B * D) + i];
    g_v[i] = s;
}

// ---------- Kernel C: register tile, 512 thr, 2 CTAs/SM ----------
// Thread (w, r, cq): rows d_i = 128*i + w*8 + r (i=0..7), cols ch*16 + 4*cq + k.
__global__ void __launch_bounds__(512, 2) main_kernel(const float* __restrict__ ctx) {
    __shared__ float red[16 * 16];
    __shared__ float ws[16];
    __shared__ float sm_acc[D];

    const int tid  = threadIdx.x;       // 512
    const int lane = tid & 31;
    const int w    = tid >> 5;          // 0..15
    const int cq   = lane & 3;          // 0..3 (float4 column group)
    const int r    = lane >> 2;         // 0..7
    const int b    = blockIdx.y;
    const int ch   = blockIdx.x;        // 0..NCH-1

    const int drow = w * 8 + r;         // 0..127
    const float* base = ctx + (size_t)b * D * C + (size_t)drow * C + ch * CCH + 4 * cq;

    // 8 independent LDG.128 -> high MLP
    float4 x[8];
#pragma unroll
    for (int i = 0; i < 8; i++)
        x[i] = *reinterpret_cast<const float4*>(base + (size_t)i * 128 * C);

    float vr[8];
#pragma unroll
    for (int i = 0; i < 8; i++)
        vr[i] = __ldg(&g_v[b * D + i * 128 + drow]);

    // Phase 1: per-column partial scores
    float p0 = 0.f, p1 = 0.f, p2 = 0.f, p3 = 0.f;
#pragma unroll
    for (int i = 0; i < 8; i++) {
        p0 += x[i].x * vr[i];  p1 += x[i].y * vr[i];
        p2 += x[i].z * vr[i];  p3 += x[i].w * vr[i];
    }
    // reduce over r (lane bits 2,3,4)
#pragma unroll
    for (int o = 4; o <= 16; o <<= 1) {
        p0 += __shfl_xor_sync(0xffffffffu, p0, o);
        p1 += __shfl_xor_sync(0xffffffffu, p1, o);
        p2 += __shfl_xor_sync(0xffffffffu, p2, o);
        p3 += __shfl_xor_sync(0xffffffffu, p3, o);
    }
    if (r == 0) {
        red[w * 16 + 4 * cq + 0] = p0;
        red[w * 16 + 4 * cq + 1] = p1;
        red[w * 16 + 4 * cq + 2] = p2;
        red[w * 16 + 4 * cq + 3] = p3;
    }
    __syncthreads();

    // warp 0, lanes 0..15: finish 16 scores + local softmax stats
    if (tid < 16) {
        float s = 0.f;
#pragma unroll
        for (int g = 0; g < 16; g++) s += red[g * 16 + tid];
        float m = s;
#pragma unroll
        for (int o = 8; o > 0; o >>= 1) m = fmaxf(m, __shfl_xor_sync(0x0000ffffu, m, o));
        float e = __expf(s - m);
        float z = e;
#pragma unroll
        for (int o = 8; o > 0; o >>= 1) z += __shfl_xor_sync(0x0000ffffu, z, o);
        ws[tid] = e;
        if (tid == 0) { g_pm[b * NCH + ch] = m; g_pz[b * NCH + ch] = z; }
    }
    __syncthreads();

    // Phase 2: weighted column sum from registers
    const float w0 = ws[4 * cq + 0], w1 = ws[4 * cq + 1];
    const float w2 = ws[4 * cq + 2], w3 = ws[4 * cq + 3];
#pragma unroll
    for (int i = 0; i < 8; i++) {
        float t = x[i].x * w0 + x[i].y * w1 + x[i].z * w2 + x[i].w * w3;
        t += __shfl_xor_sync(0xffffffffu, t, 1);
        t += __shfl_xor_sync(0xffffffffu, t, 2);
        if (cq == 0) sm_acc[i * 128 + drow] = t;
    }
    __syncthreads();
    float* dst = g_pacc + (size_t)(b * NCH + ch) * D;
    dst[tid]       = sm_acc[tid];
    dst[tid + 512] = sm_acc[tid + 512];
}

// ---------- Kernel D1: combine (float4, 32-deep MLP, split 4-way over chunks) ----------
__global__ void combine_kernel() {
    __shared__ float pmsh[NCH], pzsh[NCH], fsh[NCH];
    const int b   = blockIdx.x;
    const int chg = blockIdx.y;            // 0..NCHG-1
    const int tid = threadIdx.x;           // 256 -> one float4 (4 d's) each
    if (tid < NCH) { pmsh[tid] = g_pm[b * NCH + tid]; pzsh[tid] = g_pz[b * NCH + tid]; }
    __syncthreads();
    float M = -1e30f;
#pragma unroll 8
    for (int ch = 0; ch < NCH; ch++) M = fmaxf(M, pmsh[ch]);
    float Z = 0.f;
#pragma unroll 8
    for (int ch = 0; ch < NCH; ch++) Z += pzsh[ch] * __expf(pmsh[ch] - M);
    if (tid < NCH) fsh[tid] = __expf(pmsh[tid] - M);
    __syncthreads();
    if (chg == 0 && tid == 0) g_inv[b] = 1.0f / Z;

    float4 acc = make_float4(0.f, 0.f, 0.f, 0.f);
    const float4* src = reinterpret_cast<const float4*>(
        g_pacc + (size_t)(b * NCH + chg * CPG) * D) + tid;
#pragma unroll
    for (int j = 0; j < CPG; j++) {
        float4 p = src[(size_t)j * (D / 4)];
        float f = fsh[chg * CPG + j];
        acc.x += p.x * f; acc.y += p.y * f; acc.z += p.z * f; acc.w += p.w * f;
    }
    reinterpret_cast<float4*>(g_cpart[chg] + b * D)[tid] = acc;
}

// ---------- Kernel D2: sum partials, normalize, broadcast over seqlen ----------
__global__ void bcast_kernel(float4* __restrict__ out, int total4) {
    int i = blockIdx.x * 256 + threadIdx.x;
    if (i >= total4) return;
    int j = i & (B * D / 4 - 1);           // float4 index within one [B,D] slab
    int b = j >> 8;                        // D/4 = 256 float4 per batch row
    const float4 a0 = reinterpret_cast<const float4*>(g_cpart[0])[j];
    const float4 a1 = reinterpret_cast<const float4*>(g_cpart[1])[j];
    const float4 a2 = reinterpret_cast<const float4*>(g_cpart[2])[j];
    const float4 a3 = reinterpret_cast<const float4*>(g_cpart[3])[j];
    const float inv = g_inv[b];
    float4 o;
    o.x = (a0.x + a1.x + a2.x + a3.x) * inv;
    o.y = (a0.y + a1.y + a2.y + a3.y) * inv;
    o.z = (a0.z + a1.z + a2.z + a3.z) * inv;
    o.w = (a0.w + a1.w + a2.w + a3.w) * inv;
    out[i] = o;
}

extern "C" void kernel_launch(void* const* d_in, const int* in_sizes, int n_in,
                              void* d_out, int out_size) {
    // inputs: [0]=seqlen(int32), [1]=hidden f32 [1,B,H], [2]=contextvects f32 [B,D,C],
    //         [3]=W f32 [H,D], [4]=b f32 [H] (bias is softmax-invariant -> unused)
    const float* hid = (const float*)d_in[1];
    const float* ctx = (const float*)d_in[2];
    const float* W   = (const float*)d_in[3];

    vpart_kernel<<<dim3(8, HC), 128>>>(W, hid);
    vreduce_kernel<<<32, 1024>>>();

    main_kernel<<<dim3(NCH, B), 512>>>(ctx);

    combine_kernel<<<dim3(B, NCHG), 256>>>();

    const int total4 = out_size / 4;
    bcast_kernel<<<(total4 + 255) / 256, 256>>>((float4*)d_out, total4);
}

// round 5
// speedup vs baseline: 4.5455x; 1.0747x over previous
#include <cuda_runtime.h>

#define B    32
#define D    1024   // CTX_DIM
#define C    2048   // CTX_SIZE
#define H    1024   // HID
#define HC   32     // h-chunks in kernel A
#define HCH  (H/HC) // 32 h per chunk
#define CCH  16     // context columns per chunk in kernel C
#define NCH  (C/CCH)// 128 chunks per batch
#define NCHG 16     // combine chunk groups
#define CPG  (NCH/NCHG) // 8 chunks per group

// ---- scratch (no allocations allowed) ----
__device__ float g_pv[HC * B * D];       // 4 MB  partial v
__device__ float g_v[B * D];             // 128 KB v[b,d]
__device__ float g_pacc[B * NCH * D];    // 16 MB per-chunk weighted partial sums
__device__ float g_pm[B * NCH];          // per-chunk max
__device__ float g_pz[B * NCH];          // per-chunk Z (unnormalized)
__device__ float g_cpart[NCHG][B * D];   // combine group partials (2 MB)
__device__ float g_ctx[B * D];           // final normalized context
__device__ float g_inv[B];               // 1/Z per batch

// ---------- Kernel A: partial v[b,d] = sum_{h in chunk} W[h,d]*hidden[b,h] ----------
__global__ void vpart_kernel(const float* __restrict__ W, const float* __restrict__ hid) {
    __shared__ float sh[B][HCH];
    const int tid = threadIdx.x;                 // 128 threads
    const int d   = blockIdx.x * 128 + tid;      // 8 d-tiles
    const int h0  = blockIdx.y * HCH;            // 32 h-chunks
    for (int i = tid; i < B * HCH; i += 128) {
        int b = i / HCH, h = i % HCH;
        sh[b][h] = hid[b * H + h0 + h];
    }
    __syncthreads();
    float acc[B];
#pragma unroll
    for (int b = 0; b < B; b++) acc[b] = 0.f;
#pragma unroll 8
    for (int h = 0; h < HCH; h++) {
        float w = W[(size_t)(h0 + h) * D + d];
#pragma unroll
        for (int b = 0; b < B; b++) acc[b] += w * sh[b][h];
    }
    float* outp = g_pv + (size_t)blockIdx.y * (B * D);
#pragma unroll
    for (int b = 0; b < B; b++) outp[b * D + d] = acc[b];
}

// ---------- Kernel B: reduce partials -> g_v (float4, MLP 8) ----------
__global__ void vreduce_kernel() {
    int i = blockIdx.x * 256 + threadIdx.x;      // 32 blocks x 256 -> 8192 float4
    const float4* src = reinterpret_cast<const float4*>(g_pv) + i;
    float4 s = make_float4(0.f, 0.f, 0.f, 0.f);
#pragma unroll 8
    for (int hc = 0; hc < HC; hc++) {
        float4 p = src[(size_t)hc * (B * D / 4)];
        s.x += p.x; s.y += p.y; s.z += p.z; s.w += p.w;
    }
    reinterpret_cast<float4*>(g_v)[i] = s;
}

// ---------- Kernel C: register tile, 512 thr, 2 CTAs/SM ----------
__global__ void __launch_bounds__(512, 2) main_kernel(const float* __restrict__ ctx) {
    __shared__ float red[16 * 16];
    __shared__ float ws[16];
    __shared__ float sm_acc[D];

    const int tid  = threadIdx.x;       // 512
    const int lane = tid & 31;
    const int w    = tid >> 5;          // 0..15
    const int cq   = lane & 3;          // 0..3 (float4 column group)
    const int r    = lane >> 2;         // 0..7
    const int b    = blockIdx.y;
    const int ch   = blockIdx.x;        // 0..NCH-1

    const int drow = w * 8 + r;         // 0..127
    const float* base = ctx + (size_t)b * D * C + (size_t)drow * C + ch * CCH + 4 * cq;

    // 8 independent LDG.128, streaming (no reuse -> don't pollute L2)
    float4 x[8];
#pragma unroll
    for (int i = 0; i < 8; i++)
        x[i] = __ldcs(reinterpret_cast<const float4*>(base + (size_t)i * 128 * C));

    float vr[8];
#pragma unroll
    for (int i = 0; i < 8; i++)
        vr[i] = __ldg(&g_v[b * D + i * 128 + drow]);

    // Phase 1: per-column partial scores
    float p0 = 0.f, p1 = 0.f, p2 = 0.f, p3 = 0.f;
#pragma unroll
    for (int i = 0; i < 8; i++) {
        p0 += x[i].x * vr[i];  p1 += x[i].y * vr[i];
        p2 += x[i].z * vr[i];  p3 += x[i].w * vr[i];
    }
#pragma unroll
    for (int o = 4; o <= 16; o <<= 1) {
        p0 += __shfl_xor_sync(0xffffffffu, p0, o);
        p1 += __shfl_xor_sync(0xffffffffu, p1, o);
        p2 += __shfl_xor_sync(0xffffffffu, p2, o);
        p3 += __shfl_xor_sync(0xffffffffu, p3, o);
    }
    if (r == 0) {
        red[w * 16 + 4 * cq + 0] = p0;
        red[w * 16 + 4 * cq + 1] = p1;
        red[w * 16 + 4 * cq + 2] = p2;
        red[w * 16 + 4 * cq + 3] = p3;
    }
    __syncthreads();

    // lanes 0..15 of warp 0: finish 16 scores + local softmax stats
    if (tid < 16) {
        float s = 0.f;
#pragma unroll
        for (int g = 0; g < 16; g++) s += red[g * 16 + tid];
        float m = s;
#pragma unroll
        for (int o = 8; o > 0; o >>= 1) m = fmaxf(m, __shfl_xor_sync(0x0000ffffu, m, o));
        float e = __expf(s - m);
        float z = e;
#pragma unroll
        for (int o = 8; o > 0; o >>= 1) z += __shfl_xor_sync(0x0000ffffu, z, o);
        ws[tid] = e;
        if (tid == 0) { g_pm[b * NCH + ch] = m; g_pz[b * NCH + ch] = z; }
    }
    __syncthreads();

    // Phase 2: weighted column sum from registers
    const float w0 = ws[4 * cq + 0], w1 = ws[4 * cq + 1];
    const float w2 = ws[4 * cq + 2], w3 = ws[4 * cq + 3];
#pragma unroll
    for (int i = 0; i < 8; i++) {
        float t = x[i].x * w0 + x[i].y * w1 + x[i].z * w2 + x[i].w * w3;
        t += __shfl_xor_sync(0xffffffffu, t, 1);
        t += __shfl_xor_sync(0xffffffffu, t, 2);
        if (cq == 0) sm_acc[i * 128 + drow] = t;
    }
    __syncthreads();
    if (tid < 256) {
        float4* dst = reinterpret_cast<float4*>(g_pacc + (size_t)(b * NCH + ch) * D);
        dst[tid] = reinterpret_cast<const float4*>(sm_acc)[tid];
    }
}

// ---------- Kernel D1: combine, 16-way split, 8 independent float4 loads ----------
__global__ void combine_kernel() {
    __shared__ float pmsh[NCH], pzsh[NCH];
    __shared__ float fsh[CPG];
    const int b   = blockIdx.x;
    const int chg = blockIdx.y;            // 0..15
    const int tid = threadIdx.x;           // 256 -> one float4 each
    if (tid < NCH) { pmsh[tid] = g_pm[b * NCH + tid]; pzsh[tid] = g_pz[b * NCH + tid]; }
    __syncthreads();
    float M = -1e30f;
#pragma unroll 8
    for (int ch = 0; ch < NCH; ch++) M = fmaxf(M, pmsh[ch]);
    if (tid < CPG) fsh[tid] = __expf(pmsh[chg * CPG + tid] - M);
    if (chg == 0 && tid == 0) {
        float Z = 0.f;
        for (int ch = 0; ch < NCH; ch++) Z += pzsh[ch] * __expf(pmsh[ch] - M);
        g_inv[b] = 1.0f / Z;
    }
    __syncthreads();

    const float4* src = reinterpret_cast<const float4*>(
        g_pacc + (size_t)(b * NCH + chg * CPG) * D) + tid;
    // 8 explicit independent loads
    float4 p[CPG];
#pragma unroll
    for (int j = 0; j < CPG; j++) p[j] = src[(size_t)j * (D / 4)];
    float4 acc = make_float4(0.f, 0.f, 0.f, 0.f);
#pragma unroll
    for (int j = 0; j < CPG; j++) {
        float f = fsh[j];
        acc.x += p[j].x * f; acc.y += p[j].y * f; acc.z += p[j].z * f; acc.w += p[j].w * f;
    }
    reinterpret_cast<float4*>(g_cpart[chg] + b * D)[tid] = acc;
}

// ---------- Kernel D2a: sum the 16 group partials, normalize -> g_ctx ----------
__global__ void reduce16_kernel() {
    const int i = blockIdx.x * 256 + threadIdx.x;  // 32 blocks -> 8192 float4
    const int b = i >> 8;                          // 256 float4 per batch row
    float4 p[NCHG];
#pragma unroll
    for (int g = 0; g < NCHG; g++) p[g] = reinterpret_cast<const float4*>(g_cpart[g])[i];
    float4 s = make_float4(0.f, 0.f, 0.f, 0.f);
#pragma unroll
    for (int g = 0; g < NCHG; g++) { s.x += p[g].x; s.y += p[g].y; s.z += p[g].z; s.w += p[g].w; }
    const float inv = g_inv[b];
    s.x *= inv; s.y *= inv; s.z *= inv; s.w *= inv;
    reinterpret_cast<float4*>(g_ctx)[i] = s;
}

// ---------- Kernel D2b: broadcast over seqlen (pure write BW, g_ctx L2-resident) ----------
__global__ void bcast_kernel(float4* __restrict__ out, int total4) {
    int i = blockIdx.x * 256 + threadIdx.x;
    if (i < total4)
        out[i] = reinterpret_cast<const float4*>(g_ctx)[i & (B * D / 4 - 1)];
}

extern "C" void kernel_launch(void* const* d_in, const int* in_sizes, int n_in,
                              void* d_out, int out_size) {
    // inputs: [0]=seqlen(int32), [1]=hidden f32 [1,B,H], [2]=contextvects f32 [B,D,C],
    //         [3]=W f32 [H,D], [4]=b f32 [H] (bias is softmax-invariant -> unused)
    const float* hid = (const float*)d_in[1];
    const float* ctx = (const float*)d_in[2];
    const float* W   = (const float*)d_in[3];

    vpart_kernel<<<dim3(8, HC), 128>>>(W, hid);
    vreduce_kernel<<<32, 256>>>();

    main_kernel<<<dim3(NCH, B), 512>>>(ctx);

    combine_kernel<<<dim3(B, NCHG), 256>>>();
    reduce16_kernel<<<32, 256>>>();

    const int total4 = out_size / 4;
    bcast_kernel<<<(total4 + 255) / 256, 256>>>((float4*)d_out, total4);
}

// round 6
// speedup vs baseline: 4.6529x; 1.0236x over previous
#include <cuda_runtime.h>

#define B    32
#define D    1024   // CTX_DIM
#define C    2048   // CTX_SIZE
#define H    1024   // HID
#define HC   32     // h-chunks in kernel A
#define HCH  (H/HC) // 32 h per chunk
#define CCH  16     // context columns per chunk
#define GCH  4      // chunks per CTA (flash-style running accumulation)
#define NCHB (C/(CCH*GCH))  // 32 CTA-columns per batch
#define NCG  4      // combine split groups
#define CPG  (NCHB/NCG)     // 8 chunk-entries per combine group

// ---- scratch (no allocations allowed) ----
__device__ float g_pv[HC * B * D];       // 4 MB  partial v
__device__ float g_v[B * D];             // 128 KB v[b,d]
__device__ float g_pacc[B * NCHB * D];   // 4 MB per-CTA weighted partial sums
__device__ float g_pm[B * NCHB];         // per-CTA max
__device__ float g_pz[B * NCHB];         // per-CTA Z (unnormalized)
__device__ float g_cpart[NCG][B * D];    // combine group partials (512 KB)
__device__ float g_inv[B];               // 1/Z per batch

// ---------- Kernel A: partial v[b,d] = sum_{h in chunk} W[h,d]*hidden[b,h] ----------
__global__ void vpart_kernel(const float* __restrict__ W, const float* __restrict__ hid) {
    __shared__ float sh[B][HCH];
    const int tid = threadIdx.x;                 // 128 threads
    const int d   = blockIdx.x * 128 + tid;      // 8 d-tiles
    const int h0  = blockIdx.y * HCH;            // 32 h-chunks
    for (int i = tid; i < B * HCH; i += 128) {
        int b = i / HCH, h = i % HCH;
        sh[b][h] = hid[b * H + h0 + h];
    }
    __syncthreads();
    float acc[B];
#pragma unroll
    for (int b = 0; b < B; b++) acc[b] = 0.f;
#pragma unroll 8
    for (int h = 0; h < HCH; h++) {
        float w = W[(size_t)(h0 + h) * D + d];
#pragma unroll
        for (int b = 0; b < B; b++) acc[b] += w * sh[b][h];
    }
    float* outp = g_pv + (size_t)blockIdx.y * (B * D);
#pragma unroll
    for (int b = 0; b < B; b++) outp[b * D + d] = acc[b];
}

// ---------- Kernel B: reduce partials -> g_v (float4, MLP 8) ----------
__global__ void vreduce_kernel() {
    int i = blockIdx.x * 256 + threadIdx.x;      // 32 blocks x 256 -> 8192 float4
    const float4* src = reinterpret_cast<const float4*>(g_pv) + i;
    float4 s = make_float4(0.f, 0.f, 0.f, 0.f);
#pragma unroll 8
    for (int hc = 0; hc < HC; hc++) {
        float4 p = src[(size_t)hc * (B * D / 4)];
        s.x += p.x; s.y += p.y; s.z += p.z; s.w += p.w;
    }
    reinterpret_cast<float4*>(g_v)[i] = s;
}

// ---------- Kernel C: 4 chunks/CTA with running softmax accumulation ----------
__global__ void __launch_bounds__(512, 2) main_kernel(const float* __restrict__ ctx) {
    __shared__ float red[16 * 16];
    __shared__ float ws[16];
    __shared__ float sm_acc[D];
    __shared__ float m_sm, z_sm;

    const int tid  = threadIdx.x;       // 512
    const int lane = tid & 31;
    const int w    = tid >> 5;          // 0..15
    const int cq   = lane & 3;          // float4 column group 0..3
    const int r    = lane >> 2;         // 0..7
    const int b    = blockIdx.y;
    const int chg  = blockIdx.x;        // 0..NCHB-1

    const int drow = w * 8 + r;         // 0..127
    const float* base0 = ctx + (size_t)b * D * C + (size_t)drow * C
                       + chg * (CCH * GCH) + 4 * cq;

    float vr[8];
#pragma unroll
    for (int i = 0; i < 8; i++)
        vr[i] = __ldg(&g_v[b * D + i * 128 + drow]);

    float accA = 0.f, accB = 0.f;       // running weighted sums for d=tid, tid+512
    float m_run = -1e30f, z_run = 0.f;

    for (int g = 0; g < GCH; g++) {
        const float* base = base0 + g * CCH;
        float4 x[8];
#pragma unroll
        for (int i = 0; i < 8; i++)
            x[i] = __ldcs(reinterpret_cast<const float4*>(base + (size_t)i * 128 * C));

        // Phase 1: per-column partial scores
        float p0 = 0.f, p1 = 0.f, p2 = 0.f, p3 = 0.f;
#pragma unroll
        for (int i = 0; i < 8; i++) {
            p0 += x[i].x * vr[i];  p1 += x[i].y * vr[i];
            p2 += x[i].z * vr[i];  p3 += x[i].w * vr[i];
        }
#pragma unroll
        for (int o = 4; o <= 16; o <<= 1) {
            p0 += __shfl_xor_sync(0xffffffffu, p0, o);
            p1 += __shfl_xor_sync(0xffffffffu, p1, o);
            p2 += __shfl_xor_sync(0xffffffffu, p2, o);
            p3 += __shfl_xor_sync(0xffffffffu, p3, o);
        }
        if (r == 0) {
            red[w * 16 + 4 * cq + 0] = p0;
            red[w * 16 + 4 * cq + 1] = p1;
            red[w * 16 + 4 * cq + 2] = p2;
            red[w * 16 + 4 * cq + 3] = p3;
        }
        __syncthreads();

        // lanes 0..15: finish 16 scores + chunk softmax stats
        if (tid < 16) {
            float s = 0.f;
#pragma unroll
            for (int q = 0; q < 16; q++) s += red[q * 16 + tid];
            float m = s;
#pragma unroll
            for (int o = 8; o > 0; o >>= 1) m = fmaxf(m, __shfl_xor_sync(0x0000ffffu, m, o));
            float e = __expf(s - m);
            float z = e;
#pragma unroll
            for (int o = 8; o > 0; o >>= 1) z += __shfl_xor_sync(0x0000ffffu, z, o);
            ws[tid] = e;
            if (tid == 0) { m_sm = m; z_sm = z; }
        }
        __syncthreads();

        // Phase 2: weighted column sum from registers
        const float w0 = ws[4 * cq + 0], w1 = ws[4 * cq + 1];
        const float w2 = ws[4 * cq + 2], w3 = ws[4 * cq + 3];
#pragma unroll
        for (int i = 0; i < 8; i++) {
            float t = x[i].x * w0 + x[i].y * w1 + x[i].z * w2 + x[i].w * w3;
            t += __shfl_xor_sync(0xffffffffu, t, 1);
            t += __shfl_xor_sync(0xffffffffu, t, 2);
            if (cq == 0) sm_acc[i * 128 + drow] = t;
        }
        __syncthreads();

        // Running rescale-accumulate (all threads; scalars broadcast via smem)
        const float m_g = m_sm, z_g = z_sm;
        const float m_new = fmaxf(m_run, m_g);
        const float alpha = __expf(m_run - m_new);
        const float beta  = __expf(m_g - m_new);
        accA = accA * alpha + sm_acc[tid] * beta;
        accB = accB * alpha + sm_acc[tid + 512] * beta;
        z_run = z_run * alpha + z_g * beta;
        m_run = m_new;
        __syncthreads();   // sm_acc reused next iteration
    }

    float* dst = g_pacc + (size_t)(b * NCHB + chg) * D;
    dst[tid]       = accA;
    dst[tid + 512] = accB;
    if (tid == 0) { g_pm[b * NCHB + chg] = m_run; g_pz[b * NCHB + chg] = z_run; }
}

// ---------- Kernel D1: combine (4-way split over the 32 chunk entries) ----------
__global__ void combine_kernel() {
    __shared__ float pmsh[NCHB], pzsh[NCHB];
    __shared__ float fsh[CPG];
    const int b   = blockIdx.x;
    const int cg  = blockIdx.y;            // 0..NCG-1
    const int tid = threadIdx.x;           // 256 -> one float4 each
    if (tid < NCHB) { pmsh[tid] = g_pm[b * NCHB + tid]; pzsh[tid] = g_pz[b * NCHB + tid]; }
    __syncthreads();
    float M = -1e30f;
#pragma unroll
    for (int ch = 0; ch < NCHB; ch++) M = fmaxf(M, pmsh[ch]);
    if (tid < CPG) fsh[tid] = __expf(pmsh[cg * CPG + tid] - M);
    if (cg == 0 && tid == 0) {
        float Z = 0.f;
        for (int ch = 0; ch < NCHB; ch++) Z += pzsh[ch] * __expf(pmsh[ch] - M);
        g_inv[b] = 1.0f / Z;
    }
    __syncthreads();

    const float4* src = reinterpret_cast<const float4*>(
        g_pacc + (size_t)(b * NCHB + cg * CPG) * D) + tid;
    float4 p[CPG];
#pragma unroll
    for (int j = 0; j < CPG; j++) p[j] = src[(size_t)j * (D / 4)];
    float4 acc = make_float4(0.f, 0.f, 0.f, 0.f);
#pragma unroll
    for (int j = 0; j < CPG; j++) {
        float f = fsh[j];
        acc.x += p[j].x * f; acc.y += p[j].y * f; acc.z += p[j].z * f; acc.w += p[j].w * f;
    }
    reinterpret_cast<float4*>(g_cpart[cg] + b * D)[tid] = acc;
}

// ---------- Kernel D2: sum 4 partials + normalize + broadcast over seqlen ----------
__global__ void bcast_kernel(float4* __restrict__ out, int total4) {
    int i = blockIdx.x * 256 + threadIdx.x;
    if (i >= total4) return;
    int j = i & (B * D / 4 - 1);           // float4 index within one [B,D] slab
    int b = j >> 8;                        // D/4 = 256 float4 per batch row
    const float4 a0 = reinterpret_cast<const float4*>(g_cpart[0])[j];
    const float4 a1 = reinterpret_cast<const float4*>(g_cpart[1])[j];
    const float4 a2 = reinterpret_cast<const float4*>(g_cpart[2])[j];
    const float4 a3 = reinterpret_cast<const float4*>(g_cpart[3])[j];
    const float inv = g_inv[b];
    float4 o;
    o.x = (a0.x + a1.x + a2.x + a3.x) * inv;
    o.y = (a0.y + a1.y + a2.y + a3.y) * inv;
    o.z = (a0.z + a1.z + a2.z + a3.z) * inv;
    o.w = (a0.w + a1.w + a2.w + a3.w) * inv;
    out[i] = o;
}

extern "C" void kernel_launch(void* const* d_in, const int* in_sizes, int n_in,
                              void* d_out, int out_size) {
    // inputs: [0]=seqlen(int32), [1]=hidden f32 [1,B,H], [2]=contextvects f32 [B,D,C],
    //         [3]=W f32 [H,D], [4]=b f32 [H] (bias is softmax-invariant -> unused)
    const float* hid = (const float*)d_in[1];
    const float* ctx = (const float*)d_in[2];
    const float* W   = (const float*)d_in[3];

    vpart_kernel<<<dim3(8, HC), 128>>>(W, hid);
    vreduce_kernel<<<32, 256>>>();

    main_kernel<<<dim3(NCHB, B), 512>>>(ctx);

    combine_kernel<<<dim3(B, NCG), 256>>>();

    const int total4 = out_size / 4;
    bcast_kernel<<<(total4 + 255) / 256, 256>>>((float4*)d_out, total4);
}